// round 15
// baseline (speedup 1.0000x reference)
#include <cuda_runtime.h>
#include <cuda_fp16.h>
#include <cmath>
#include <cstdint>

// ---------------- problem constants ----------------
#define BT    8192
#define DDIM  4096
#define NH    512
#define NDD   128
#define NTOT  640
#define KDIM  128

#define W2_BASE  (BT * 4 * 2 * 32)   // 2,097,152
#define DD_BASE  (2 * W2_BASE)

// ---------------- device scratch ----------------
__device__ __half g_Wh[(size_t)NTOT * DDIM];      // [n][k] fp16 (hidden 0..511, dd 512..639)
__device__ __half g_Qh[4 * KDIM * KDIM];          // qkwT fp16: [c][j][k]

__device__ __forceinline__ float gelu_exact(float x) {
    return 0.5f * x * (1.0f + erff(x * 0.70710678118654752f));
}

#define CPA16(dst, src) \
    asm volatile("cp.async.cg.shared.global [%0], [%1], 16;" :: "r"(dst), "l"(src) : "memory")
#define CPA_COMMIT() asm volatile("cp.async.commit_group;" ::: "memory")
#define CPA_WAIT2()  asm volatile("cp.async.wait_group 2;" ::: "memory")
#define CPA_WAIT1()  asm volatile("cp.async.wait_group 1;" ::: "memory")
#define CPA_WAIT0()  asm volatile("cp.async.wait_group 0;" ::: "memory")

__device__ __forceinline__ uint32_t smem_u32(const void* p) {
    uint32_t a;
    asm("{ .reg .u64 t; cvta.to.shared.u64 t, %1; cvt.u32.u64 %0, t; }" : "=r"(a) : "l"(p));
    return a;
}

__device__ __forceinline__ void mma16816(float* d, const uint32_t* a, const uint32_t* b) {
    asm volatile(
        "mma.sync.aligned.m16n8k16.row.col.f32.f16.f16.f32 "
        "{%0,%1,%2,%3}, {%4,%5,%6,%7}, {%8,%9}, {%0,%1,%2,%3};"
        : "+f"(d[0]), "+f"(d[1]), "+f"(d[2]), "+f"(d[3])
        : "r"(a[0]), "r"(a[1]), "r"(a[2]), "r"(a[3]), "r"(b[0]), "r"(b[1]));
}

__device__ __forceinline__ void ldsm_x4(uint32_t addr, uint32_t* r) {
    asm volatile("ldmatrix.sync.aligned.m8n8.x4.shared.b16 {%0,%1,%2,%3}, [%4];"
        : "=r"(r[0]), "=r"(r[1]), "=r"(r[2]), "=r"(r[3]) : "r"(addr));
}

__device__ __forceinline__ void ldsm_x2(uint32_t addr, uint32_t* r) {
    asm volatile("ldmatrix.sync.aligned.m8n8.x2.shared.b16 {%0,%1}, [%2];"
        : "=r"(r[0]), "=r"(r[1]) : "r"(addr));
}

__device__ __forceinline__ uint32_t pack_h2(float a, float b) {
    __half2 h = __floats2half2_rn(a, b);
    return *reinterpret_cast<uint32_t*>(&h);
}

// ---------------------------------------------------------------------------
// conv_wq: merged weight-prep kernel.
//   blocks [0, 2560):   transpose [dw1 | dd_p] -> g_Wh [640][4096] fp16
//   blocks [2560, 2624): transpose qkw [c][k][j] -> g_Qh [c][j][k] fp16
// ---------------------------------------------------------------------------
__global__ __launch_bounds__(256) void conv_wq(const float* __restrict__ dw1,
                                               const float* __restrict__ ddp,
                                               const float* __restrict__ qkw) {
    __shared__ float t[32][33];
    int tx = threadIdx.x, ty = threadIdx.y;   // 32 x 8
    int bid = blockIdx.x;

    if (bid < 2560) {
        int n0 = (bid % 20) * 32, k0 = (bid / 20) * 32;
        const float* src = (n0 < NH) ? dw1 : ddp;
        int ld   = (n0 < NH) ? NH : NDD;
        int ncol = (n0 < NH) ? (n0 + tx) : (n0 - NH + tx);
        #pragma unroll
        for (int j = 0; j < 4; ++j)
            t[ty + 8 * j][tx] = src[(size_t)(k0 + ty + 8 * j) * ld + ncol];
        __syncthreads();
        #pragma unroll
        for (int j = 0; j < 4; ++j) {
            int n = n0 + ty + 8 * j, k = k0 + tx;
            g_Wh[(size_t)n * DDIM + k] = __float2half_rn(t[tx][ty + 8 * j]);
        }
    } else {
        int qb = bid - 2560;                 // 0..63
        int c  = qb >> 4;
        int j0 = ((qb >> 2) & 3) * 32;
        int k0 = (qb & 3) * 32;
        #pragma unroll
        for (int jj = 0; jj < 4; ++jj)
            t[ty + 8 * jj][tx] = qkw[((c * KDIM) + (k0 + ty + 8 * jj)) * KDIM + j0 + tx];
        __syncthreads();
        #pragma unroll
        for (int jj = 0; jj < 4; ++jj) {
            int j = j0 + ty + 8 * jj, k = k0 + tx;
            g_Qh[(c * KDIM + j) * KDIM + k] = __float2half_rn(t[tx][ty + 8 * jj]);
        }
    }
}

// ---------------------------------------------------------------------------
// gemm_all: 512 CTAs, 256 threads, occ 3 (24 warps/SM). CTA (ntile, mbase):
//   hidden cols [ntile*128, +128) x 64 rows  -> fused 2nd GEMM + RMS -> w1n/w2
//   dd cols     [ntile*32,  +32)  x 64 rows  -> tanh -> dd
// Warp grid 2M x 4N: hidden warp tile 32x32, dd warp tile 32x8.
// Smem (48K): mainloop A 2x4K [0,8K) + W 4x10K [8K,48K) (W tile = 160 rows);
// epilogue Ahi [0,16K), Q double-buffer [16K,32K)+[32K,48K).
// ---------------------------------------------------------------------------
#define ABUF_B  4096
#define WST_B   10240
#define W_OFF   8192
#define GEMM1_SMEM 49152

__global__ __launch_bounds__(256, 3) void gemm_all(
    const float* __restrict__ X,
    float* __restrict__ w1n_out, float* __restrict__ w2_out,
    float* __restrict__ dd_out) {
    extern __shared__ char smem[];
    uint32_t sb = smem_u32(smem);

    const int tid  = threadIdx.x;
    const int wid  = tid >> 5;
    const int lane = tid & 31;
    const int gq   = lane >> 2;
    const int tg   = lane & 3;

    const int ntile = blockIdx.x;          // 0..3
    const int mbase = blockIdx.y << 6;     // 64-row tiles
    const int m0w   = (wid & 1) * 32;      // 2 M-warps
    const int nwid  = wid >> 1;            // 4 N-warps
    const int n0w   = nwid * 32;

    const float* Xrow = X + (size_t)mbase * DDIM;

    // A LDG geometry: 64 rows x 32 k f32 = 512 16B chunks -> 2 per thread
    uint32_t aSrcOff[2];   // byte offsets into Xrow
    uint32_t aSts[2];
    #pragma unroll
    for (int q = 0; q < 2; ++q) {
        int cc = tid + q * 256;
        int r = cc >> 3, ch = cc & 7;
        aSrcOff[q] = (uint32_t)(r * DDIM * 4 + ch * 16);
        aSts[q] = (uint32_t)(r * 64
                + ((((ch >> 1) ^ ((r >> 1) & 3)) << 4) + ((ch & 1) << 3)));
    }
    // W cp.async geometry: 160 rows x 64B = 640 chunks -> 3 per thread (pred)
    uint32_t wDst[3], wSrcOff[3];   // byte offsets into g_Wh
    #pragma unroll
    for (int q = 0; q < 3; ++q) {
        int cc = tid + q * 256;
        int r = (cc < 640) ? (cc >> 2) : 0;
        int ch = cc & 3;
        wDst[q] = (uint32_t)(r * 64 + ((ch ^ ((r >> 1) & 3)) << 4));
        int grow = (r < 128) ? (ntile * 128 + r) : (NH + ntile * 32 + (r - 128));
        wSrcOff[q] = (uint32_t)(grow * DDIM * 2 + ch * 16);
    }
    const char* whBase = reinterpret_cast<const char*>(g_Wh);

    auto w_refill = [&](uint32_t stg, int k0) {
        #pragma unroll
        for (int q = 0; q < 2; ++q)
            CPA16(stg + wDst[q], whBase + wSrcOff[q] + k0 * 2);
        if (tid + 512 < 640)
            CPA16(stg + wDst[2], whBase + wSrcOff[2] + k0 * 2);
    };

    float4 xreg[2];
    auto a_ldg = [&](int k0) {
        #pragma unroll
        for (int q = 0; q < 2; ++q)
            xreg[q] = *reinterpret_cast<const float4*>(
                reinterpret_cast<const char*>(Xrow) + aSrcOff[q] + k0 * 4);
    };
    auto a_sts = [&](uint32_t abuf) {
        #pragma unroll
        for (int q = 0; q < 2; ++q) {
            float4 v = xreg[q];
            uint32_t h0 = pack_h2(v.x, v.y), h1 = pack_h2(v.z, v.w);
            uint32_t a = abuf + aSts[q];
            asm volatile("st.shared.v2.u32 [%0], {%1,%2};" :: "r"(a), "r"(h0), "r"(h1) : "memory");
        }
    };

    // ldmatrix lane geometry
    const int rowAoff = ((lane >> 3) & 1) * 8 + (lane & 7);
    const int cAoff   = (lane >> 4) & 1;
    const int rowBoff = ((lane >> 4) & 1) * 8 + (lane & 7);
    const int cBoff   = (lane >> 3) & 1;
    // dd x2 frag geometry (lanes 0..15 used)
    const int rowDoff = lane & 7;
    const int cDoff   = (lane >> 3) & 1;

    // ---- prologue ----
    a_ldg(0);
    a_sts(sb);
    a_ldg(32);
    w_refill(sb + W_OFF, 0);              CPA_COMMIT();
    w_refill(sb + W_OFF + WST_B, 32);     CPA_COMMIT();
    w_refill(sb + W_OFF + 2 * WST_B, 64); CPA_COMMIT();

    float acc[2][4][4];     // hidden: 32 cols
    float accD[2][4];       // dd: 8 cols
    #pragma unroll
    for (int mi = 0; mi < 2; ++mi) {
        #pragma unroll
        for (int ni = 0; ni < 4; ++ni)
            #pragma unroll
            for (int r = 0; r < 4; ++r) acc[mi][ni][r] = 0.0f;
        #pragma unroll
        for (int r = 0; r < 4; ++r) accD[mi][r] = 0.0f;
    }

    const int NKT = DDIM / 32;  // 128

    for (int it = 0; it < NKT; ++it) {
        uint32_t abuf = sb + (uint32_t)(it & 1) * ABUF_B;
        uint32_t wstg = sb + W_OFF + (uint32_t)(it & 3) * WST_B;

        CPA_WAIT2();
        __syncthreads();

        if (it + 1 < NKT) a_sts(sb + (uint32_t)((it + 1) & 1) * ABUF_B);
        if (it + 2 < NKT) a_ldg((it + 2) * 32);

        #pragma unroll
        for (int ks = 0; ks < 2; ++ks) {
            int c0 = ks * 2;
            uint32_t bh[4][2], bd[2];
            #pragma unroll
            for (int p = 0; p < 2; ++p) {
                int rowB = n0w + p * 16 + rowBoff;
                int cB   = c0 + cBoff;
                uint32_t aW = wstg + rowB * 64
                            + (uint32_t)((cB ^ ((rowB >> 1) & 3)) << 4);
                uint32_t t[4];
                ldsm_x4(aW, t);
                bh[2*p][0] = t[0]; bh[2*p][1] = t[1];
                bh[2*p+1][0] = t[2]; bh[2*p+1][1] = t[3];
            }
            {   // dd W frag: rows 128 + nwid*8 .. +8 (x2)
                int rowD = 128 + nwid * 8 + rowDoff;
                int cD   = c0 + cDoff;
                uint32_t aD = wstg + rowD * 64
                            + (uint32_t)((cD ^ ((rowD >> 1) & 3)) << 4);
                ldsm_x2(aD, bd);
            }
            #pragma unroll
            for (int mi = 0; mi < 2; ++mi) {
                int rowA = m0w + mi * 16 + rowAoff;
                int cA   = c0 + cAoff;
                uint32_t aA = abuf + rowA * 64
                            + (uint32_t)((cA ^ ((rowA >> 1) & 3)) << 4);
                uint32_t ah[4];
                ldsm_x4(aA, ah);
                #pragma unroll
                for (int ni = 0; ni < 4; ++ni)
                    mma16816(acc[mi][ni], ah, bh[ni]);
                mma16816(accD[mi], ah, bd);
            }
        }

        if (it + 3 < NKT)
            w_refill(sb + W_OFF + (uint32_t)((it + 3) & 3) * WST_B, (it + 3) * 32);
        CPA_COMMIT();
    }

    CPA_WAIT0();
    __syncthreads();

    // ---- dd epilogue first (frees accD registers) ----
    #pragma unroll
    for (int mi = 0; mi < 2; ++mi) {
        int row = mbase + m0w + mi * 16 + gq;
        int col = ntile * 32 + nwid * 8 + tg * 2;
        float2 o0 = make_float2(tanhf(accD[mi][0]), tanhf(accD[mi][1]));
        float2 o1 = make_float2(tanhf(accD[mi][2]), tanhf(accD[mi][3]));
        *reinterpret_cast<float2*>(&dd_out[(size_t)row * NDD + col])       = o0;
        *reinterpret_cast<float2*>(&dd_out[(size_t)(row + 8) * NDD + col]) = o1;
    }

    // ================= fused hidden epilogue =================
    const int c = ntile;
    const uint32_t qb0 = sb + 16384;   // Q kb=0 [16K,32K)
    const uint32_t qb1 = sb + 32768;   // Q kb=1 [32K,48K)

    // Issue BOTH Q halves now; they land under the gelu/STS phase below.
    // Each half: 128 rows x 128B = 1024 chunks -> 4 per thread.
    #pragma unroll
    for (int q = 0; q < 4; ++q) {
        int cc = tid + q * 256;
        int j  = cc >> 3, ch = cc & 7;
        uint32_t off = (uint32_t)(j * 128 + ((ch ^ (j & 7)) << 4));
        CPA16(qb0 + off, g_Qh + ((size_t)(c * KDIM + j)) * KDIM + ch * 8);
    }
    CPA_COMMIT();
    #pragma unroll
    for (int q = 0; q < 4; ++q) {
        int cc = tid + q * 256;
        int j  = cc >> 3, ch = cc & 7;
        uint32_t off = (uint32_t)(j * 128 + ((ch ^ (j & 7)) << 4));
        CPA16(qb1 + off, g_Qh + ((size_t)(c * KDIM + j)) * KDIM + 64 + ch * 8);
    }
    CPA_COMMIT();

    // Phase 1: gelu -> fp16 single-term into Ahi [0,16K)
    // rows 256B (128 fp16), 16 chunks, swizzle ch ^ (row&7)
    #pragma unroll
    for (int mi = 0; mi < 2; ++mi) {
        #pragma unroll
        for (int ni = 0; ni < 4; ++ni) {
            int row0 = m0w + mi * 16 + gq;
            int col  = n0w + ni * 8 + tg * 2;
            uint32_t ch = (uint32_t)(col >> 3);
            uint32_t wi = (uint32_t)((col & 7) * 2);
            #pragma unroll
            for (int r2 = 0; r2 < 2; ++r2) {
                int row = row0 + r2 * 8;
                float v0 = gelu_exact(acc[mi][ni][2 * r2 + 0]);
                float v1 = gelu_exact(acc[mi][ni][2 * r2 + 1]);
                uint32_t h = pack_h2(v0, v1);
                uint32_t a = sb + row * 256 + ((ch ^ (uint32_t)(row & 7)) << 4) + wi;
                asm volatile("st.shared.u32 [%0], %1;" :: "r"(a), "r"(h) : "memory");
            }
        }
    }

    // Phase 2: 64x128x128 single-term MMA (hh*qh), f32 acc, Q double-buffered
    float acc2[2][4][4];
    #pragma unroll
    for (int mi = 0; mi < 2; ++mi)
        #pragma unroll
        for (int ni = 0; ni < 4; ++ni)
            #pragma unroll
            for (int r = 0; r < 4; ++r) acc2[mi][ni][r] = 0.0f;

    for (int kb = 0; kb < 2; ++kb) {
        uint32_t qb = kb ? qb1 : qb0;
        if (kb == 0) { CPA_WAIT1(); } else { CPA_WAIT0(); }
        __syncthreads();   // Q half visible + phase-1 STS visible (kb0)

        #pragma unroll
        for (int ksl = 0; ksl < 4; ++ksl) {
            uint32_t qh[4][2];
            #pragma unroll
            for (int p = 0; p < 2; ++p) {
                int rowB = n0w + p * 16 + rowBoff;
                int cB   = ksl * 2 + cBoff;
                uint32_t aW = qb + rowB * 128
                            + (uint32_t)((cB ^ (rowB & 7)) << 4);
                uint32_t t[4];
                ldsm_x4(aW, t);
                qh[2*p][0] = t[0]; qh[2*p][1] = t[1];
                qh[2*p+1][0] = t[2]; qh[2*p+1][1] = t[3];
            }
            #pragma unroll
            for (int mi = 0; mi < 2; ++mi) {
                int rowA = m0w + mi * 16 + rowAoff;
                int cA   = kb * 8 + ksl * 2 + cAoff;
                uint32_t aA = sb + rowA * 256
                            + (uint32_t)((cA ^ (rowA & 7)) << 4);
                uint32_t ah[4];
                ldsm_x4(aA, ah);
                #pragma unroll
                for (int ni = 0; ni < 4; ++ni)
                    mma16816(acc2[mi][ni], ah, qh[ni]);
            }
        }
    }

    // Phase 3: RMS over M=32 (warp's 32 cols = one ii group) + stores
    const int ii = nwid;   // 0..3
    #pragma unroll
    for (int mi = 0; mi < 2; ++mi) {
        #pragma unroll
        for (int r2 = 0; r2 < 2; ++r2) {
            int r = mbase + m0w + mi * 16 + gq + r2 * 8;
            float ss = 0.0f;
            #pragma unroll
            for (int ni = 0; ni < 4; ++ni) {
                ss = fmaf(acc2[mi][ni][2*r2+0], acc2[mi][ni][2*r2+0], ss);
                ss = fmaf(acc2[mi][ni][2*r2+1], acc2[mi][ni][2*r2+1], ss);
            }
            ss += __shfl_xor_sync(0xffffffffu, ss, 1);
            ss += __shfl_xor_sync(0xffffffffu, ss, 2);

            if (ii < 2) {
                float scale = rsqrtf(ss * (1.0f / 32.0f) + 1e-6f);
                #pragma unroll
                for (int ni = 0; ni < 4; ++ni) {
                    int m = ni * 8 + tg * 2;
                    float2 o = make_float2(acc2[mi][ni][2*r2+0] * scale,
                                           acc2[mi][ni][2*r2+1] * scale);
                    *reinterpret_cast<float2*>(
                        &w1n_out[(size_t)r * 256 + c * 64 + ii * 32 + m]) = o;
                }
            } else {
                #pragma unroll
                for (int ni = 0; ni < 4; ++ni) {
                    int m = ni * 8 + tg * 2;
                    float2 o = make_float2(acc2[mi][ni][2*r2+0],
                                           acc2[mi][ni][2*r2+1]);
                    *reinterpret_cast<float2*>(
                        &w2_out[(size_t)r * 256 + c * 64 + (ii - 2) * 32 + m]) = o;
                }
            }
        }
    }
}

// ---------------------------------------------------------------------------
extern "C" void kernel_launch(void* const* d_in, const int* in_sizes, int n_in,
                              void* d_out, int out_size) {
    const float* query = (const float*)d_in[0];
    // d_in[1] = key_vec (unused by reference)
    const float* dw1   = (const float*)d_in[2];
    const float* qkw   = (const float*)d_in[3];
    const float* dd_p  = (const float*)d_in[4];

    float* out = (float*)d_out;
    float* w1n = out;
    float* w2  = out + W2_BASE;
    float* dd  = out + DD_BASE;

    cudaFuncSetAttribute(gemm_all, cudaFuncAttributeMaxDynamicSharedMemorySize, GEMM1_SMEM);

    conv_wq<<<2624, dim3(32, 8)>>>(dw1, dd_p, qkw);
    gemm_all<<<dim3(4, 128), 256, GEMM1_SMEM>>>(query, w1n, w2, dd);
}

// round 16
// speedup vs baseline: 1.4935x; 1.4935x over previous
#include <cuda_runtime.h>
#include <cuda_fp16.h>
#include <cmath>
#include <cstdint>

// ---------------- problem constants ----------------
#define BT    8192
#define DDIM  4096
#define NH    512
#define NDD   128
#define NTOT  640
#define KDIM  128

#define W2_BASE  (BT * 4 * 2 * 32)   // 2,097,152
#define DD_BASE  (2 * W2_BASE)

// ---------------- device scratch ----------------
__device__ __half g_Wh[(size_t)NTOT * DDIM];      // [n][k] fp16 (hidden 0..511, dd 512..639)
__device__ __half g_Qh[4 * KDIM * KDIM];          // qkwT fp16: [c][j][k]

__device__ __forceinline__ float gelu_exact(float x) {
    return 0.5f * x * (1.0f + erff(x * 0.70710678118654752f));
}

#define CPA16(dst, src) \
    asm volatile("cp.async.cg.shared.global [%0], [%1], 16;" :: "r"(dst), "l"(src) : "memory")
#define CPA_COMMIT() asm volatile("cp.async.commit_group;" ::: "memory")
#define CPA_WAIT2()  asm volatile("cp.async.wait_group 2;" ::: "memory")
#define CPA_WAIT1()  asm volatile("cp.async.wait_group 1;" ::: "memory")
#define CPA_WAIT0()  asm volatile("cp.async.wait_group 0;" ::: "memory")

__device__ __forceinline__ uint32_t smem_u32(const void* p) {
    uint32_t a;
    asm("{ .reg .u64 t; cvta.to.shared.u64 t, %1; cvt.u32.u64 %0, t; }" : "=r"(a) : "l"(p));
    return a;
}

__device__ __forceinline__ void mma16816(float* d, const uint32_t* a, const uint32_t* b) {
    asm volatile(
        "mma.sync.aligned.m16n8k16.row.col.f32.f16.f16.f32 "
        "{%0,%1,%2,%3}, {%4,%5,%6,%7}, {%8,%9}, {%0,%1,%2,%3};"
        : "+f"(d[0]), "+f"(d[1]), "+f"(d[2]), "+f"(d[3])
        : "r"(a[0]), "r"(a[1]), "r"(a[2]), "r"(a[3]), "r"(b[0]), "r"(b[1]));
}

__device__ __forceinline__ void ldsm_x4(uint32_t addr, uint32_t* r) {
    asm volatile("ldmatrix.sync.aligned.m8n8.x4.shared.b16 {%0,%1,%2,%3}, [%4];"
        : "=r"(r[0]), "=r"(r[1]), "=r"(r[2]), "=r"(r[3]) : "r"(addr));
}

__device__ __forceinline__ void ldsm_x2(uint32_t addr, uint32_t* r) {
    asm volatile("ldmatrix.sync.aligned.m8n8.x2.shared.b16 {%0,%1}, [%2];"
        : "=r"(r[0]), "=r"(r[1]) : "r"(addr));
}

__device__ __forceinline__ uint32_t pack_h2(float a, float b) {
    __half2 h = __floats2half2_rn(a, b);
    return *reinterpret_cast<uint32_t*>(&h);
}

// ---------------------------------------------------------------------------
// conv_wq: merged weight-prep kernel.
//   blocks [0, 2560):   transpose [dw1 | dd_p] -> g_Wh [640][4096] fp16
//   blocks [2560, 2624): transpose qkw [c][k][j] -> g_Qh [c][j][k] fp16
// ---------------------------------------------------------------------------
__global__ __launch_bounds__(256) void conv_wq(const float* __restrict__ dw1,
                                               const float* __restrict__ ddp,
                                               const float* __restrict__ qkw) {
    __shared__ float t[32][33];
    int tx = threadIdx.x, ty = threadIdx.y;   // 32 x 8
    int bid = blockIdx.x;

    if (bid < 2560) {
        int n0 = (bid % 20) * 32, k0 = (bid / 20) * 32;
        const float* src = (n0 < NH) ? dw1 : ddp;
        int ld   = (n0 < NH) ? NH : NDD;
        int ncol = (n0 < NH) ? (n0 + tx) : (n0 - NH + tx);
        #pragma unroll
        for (int j = 0; j < 4; ++j)
            t[ty + 8 * j][tx] = src[(size_t)(k0 + ty + 8 * j) * ld + ncol];
        __syncthreads();
        #pragma unroll
        for (int j = 0; j < 4; ++j) {
            int n = n0 + ty + 8 * j, k = k0 + tx;
            g_Wh[(size_t)n * DDIM + k] = __float2half_rn(t[tx][ty + 8 * j]);
        }
    } else {
        int qb = bid - 2560;                 // 0..63
        int c  = qb >> 4;
        int j0 = ((qb >> 2) & 3) * 32;
        int k0 = (qb & 3) * 32;
        #pragma unroll
        for (int jj = 0; jj < 4; ++jj)
            t[ty + 8 * jj][tx] = qkw[((c * KDIM) + (k0 + ty + 8 * jj)) * KDIM + j0 + tx];
        __syncthreads();
        #pragma unroll
        for (int jj = 0; jj < 4; ++jj) {
            int j = j0 + ty + 8 * jj, k = k0 + tx;
            g_Qh[(c * KDIM + j) * KDIM + k] = __float2half_rn(t[tx][ty + 8 * jj]);
        }
    }
}

// ---------------------------------------------------------------------------
// gemm_all: 512 CTAs (one occ-4 wave), 128 threads. CTA (ntile, mbase):
//   hidden cols [ntile*128, +128) x 64 rows  -> fused 2nd GEMM + RMS -> w1n/w2
//   dd cols     [ntile*32,  +32)  x 64 rows  -> tanh -> dd
// Warp grid 1M x 4N: warp tile 64 rows x (32 hidden + 8 dd) cols.
// B frags loaded ONCE per CTA (no M-dup); A frags loaded per warp (x4 dup).
// Smem (48K): mainloop A 2x4K [0,8K) + W 4x10K [8K,48K) (W tile = 160 rows);
// epilogue Ahi [0,16K), Q double-buffer [16K,32K)+[32K,48K).
// ---------------------------------------------------------------------------
#define ABUF_B  4096
#define WST_B   10240
#define W_OFF   8192
#define GEMM1_SMEM 49152

__global__ __launch_bounds__(128, 4) void gemm_all(
    const float* __restrict__ X,
    float* __restrict__ w1n_out, float* __restrict__ w2_out,
    float* __restrict__ dd_out) {
    extern __shared__ char smem[];
    uint32_t sb = smem_u32(smem);

    const int tid  = threadIdx.x;
    const int wid  = tid >> 5;
    const int lane = tid & 31;
    const int gq   = lane >> 2;
    const int tg   = lane & 3;

    const int ntile = blockIdx.x;          // 0..3
    const int mbase = blockIdx.y << 6;     // 64-row tiles
    const int n0w   = wid * 32;            // warp hidden-col offset

    const float* Xrow = X + (size_t)mbase * DDIM;

    // A LDG geometry: 64 rows x 32 k f32 = 512 16B chunks -> 4 per thread
    int aRow[4], aCh[4];
    uint32_t aSts[4];
    #pragma unroll
    for (int q = 0; q < 4; ++q) {
        int cc = tid + q * 128;
        aRow[q] = cc >> 3; aCh[q] = cc & 7;
        aSts[q] = (uint32_t)(aRow[q] * 64
                + ((((aCh[q] >> 1) ^ ((aRow[q] >> 1) & 3)) << 4) + ((aCh[q] & 1) << 3)));
    }
    // W cp.async geometry: 160 rows x 64B = 640 chunks -> 5 per thread
    uint32_t wDst[5];
    const __half* wSrc[5];
    #pragma unroll
    for (int q = 0; q < 5; ++q) {
        int cc = tid + q * 128;
        int r = cc >> 2, ch = cc & 3;
        wDst[q] = (uint32_t)(r * 64 + ((ch ^ ((r >> 1) & 3)) << 4));
        int grow = (r < 128) ? (ntile * 128 + r) : (NH + ntile * 32 + (r - 128));
        wSrc[q] = g_Wh + (size_t)grow * DDIM + ch * 8;
    }

    auto w_refill = [&](uint32_t stg, int k0) {
        #pragma unroll
        for (int q = 0; q < 5; ++q)
            CPA16(stg + wDst[q], wSrc[q] + k0);
    };

    float4 xreg[4];
    auto a_ldg = [&](int k0) {
        #pragma unroll
        for (int q = 0; q < 4; ++q)
            xreg[q] = *reinterpret_cast<const float4*>(
                &Xrow[(size_t)aRow[q] * DDIM + k0 + aCh[q] * 4]);
    };
    auto a_sts = [&](uint32_t abuf) {
        #pragma unroll
        for (int q = 0; q < 4; ++q) {
            float4 v = xreg[q];
            uint32_t h0 = pack_h2(v.x, v.y), h1 = pack_h2(v.z, v.w);
            uint32_t a = abuf + aSts[q];
            asm volatile("st.shared.v2.u32 [%0], {%1,%2};" :: "r"(a), "r"(h0), "r"(h1) : "memory");
        }
    };

    // ldmatrix lane geometry
    const int rowAoff = ((lane >> 3) & 1) * 8 + (lane & 7);
    const int cAoff   = (lane >> 4) & 1;
    const int rowBoff = ((lane >> 4) & 1) * 8 + (lane & 7);
    const int cBoff   = (lane >> 3) & 1;
    // dd x2 frag geometry (lanes 0..15 used)
    const int rowDoff = lane & 7;
    const int cDoff   = (lane >> 3) & 1;

    // ---- prologue ----
    a_ldg(0);
    a_sts(sb);
    a_ldg(32);
    w_refill(sb + W_OFF, 0);              CPA_COMMIT();
    w_refill(sb + W_OFF + WST_B, 32);     CPA_COMMIT();
    w_refill(sb + W_OFF + 2 * WST_B, 64); CPA_COMMIT();

    float acc[4][4][4];     // hidden: 64 rows x 32 cols
    float accD[4][4];       // dd: 64 rows x 8 cols
    #pragma unroll
    for (int mi = 0; mi < 4; ++mi) {
        #pragma unroll
        for (int ni = 0; ni < 4; ++ni)
            #pragma unroll
            for (int r = 0; r < 4; ++r) acc[mi][ni][r] = 0.0f;
        #pragma unroll
        for (int r = 0; r < 4; ++r) accD[mi][r] = 0.0f;
    }

    const int NKT = DDIM / 32;  // 128

    for (int it = 0; it < NKT; ++it) {
        uint32_t abuf = sb + (uint32_t)(it & 1) * ABUF_B;
        uint32_t wstg = sb + W_OFF + (uint32_t)(it & 3) * WST_B;

        CPA_WAIT2();
        __syncthreads();

        if (it + 1 < NKT) a_sts(sb + (uint32_t)((it + 1) & 1) * ABUF_B);
        if (it + 2 < NKT) a_ldg((it + 2) * 32);

        #pragma unroll
        for (int ks = 0; ks < 2; ++ks) {
            int c0 = ks * 2;
            uint32_t bh[4][2], bd[2];
            #pragma unroll
            for (int p = 0; p < 2; ++p) {
                int rowB = n0w + p * 16 + rowBoff;
                int cB   = c0 + cBoff;
                uint32_t aW = wstg + rowB * 64
                            + (uint32_t)((cB ^ ((rowB >> 1) & 3)) << 4);
                uint32_t t[4];
                ldsm_x4(aW, t);
                bh[2*p][0] = t[0]; bh[2*p][1] = t[1];
                bh[2*p+1][0] = t[2]; bh[2*p+1][1] = t[3];
            }
            {   // dd W frag: rows 128 + wid*8 .. +8 (x2)
                int rowD = 128 + wid * 8 + rowDoff;
                int cD   = c0 + cDoff;
                uint32_t aD = wstg + rowD * 64
                            + (uint32_t)((cD ^ ((rowD >> 1) & 3)) << 4);
                ldsm_x2(aD, bd);
            }
            #pragma unroll
            for (int mi = 0; mi < 4; ++mi) {
                int rowA = mi * 16 + rowAoff;
                int cA   = c0 + cAoff;
                uint32_t aA = abuf + rowA * 64
                            + (uint32_t)((cA ^ ((rowA >> 1) & 3)) << 4);
                uint32_t ah[4];
                ldsm_x4(aA, ah);
                #pragma unroll
                for (int ni = 0; ni < 4; ++ni)
                    mma16816(acc[mi][ni], ah, bh[ni]);
                mma16816(accD[mi], ah, bd);
            }
        }

        if (it + 3 < NKT)
            w_refill(sb + W_OFF + (uint32_t)((it + 3) & 3) * WST_B, (it + 3) * 32);
        CPA_COMMIT();
    }

    CPA_WAIT0();
    __syncthreads();

    // ---- dd epilogue first (frees accD registers) ----
    #pragma unroll
    for (int mi = 0; mi < 4; ++mi) {
        int row = mbase + mi * 16 + gq;
        int col = ntile * 32 + wid * 8 + tg * 2;
        float2 o0 = make_float2(tanhf(accD[mi][0]), tanhf(accD[mi][1]));
        float2 o1 = make_float2(tanhf(accD[mi][2]), tanhf(accD[mi][3]));
        *reinterpret_cast<float2*>(&dd_out[(size_t)row * NDD + col])       = o0;
        *reinterpret_cast<float2*>(&dd_out[(size_t)(row + 8) * NDD + col]) = o1;
    }

    // ================= fused hidden epilogue =================
    const int c = ntile;
    const uint32_t qb0 = sb + 16384;   // Q kb=0 [16K,32K)
    const uint32_t qb1 = sb + 32768;   // Q kb=1 [32K,48K)

    // Issue BOTH Q halves now; they land under the gelu/STS phase below.
    #pragma unroll
    for (int q = 0; q < 8; ++q) {
        int cc = tid + q * 128;
        int j  = cc >> 3, ch = cc & 7;
        uint32_t off = (uint32_t)(j * 128 + ((ch ^ (j & 7)) << 4));
        CPA16(qb0 + off, g_Qh + ((size_t)(c * KDIM + j)) * KDIM + ch * 8);
    }
    CPA_COMMIT();
    #pragma unroll
    for (int q = 0; q < 8; ++q) {
        int cc = tid + q * 128;
        int j  = cc >> 3, ch = cc & 7;
        uint32_t off = (uint32_t)(j * 128 + ((ch ^ (j & 7)) << 4));
        CPA16(qb1 + off, g_Qh + ((size_t)(c * KDIM + j)) * KDIM + 64 + ch * 8);
    }
    CPA_COMMIT();

    // Phase 1: gelu -> fp16 single-term into Ahi [0,16K)
    // rows 256B (128 fp16), 16 chunks, swizzle ch ^ (row&7)
    #pragma unroll
    for (int mi = 0; mi < 4; ++mi) {
        #pragma unroll
        for (int ni = 0; ni < 4; ++ni) {
            int row0 = mi * 16 + gq;
            int col  = n0w + ni * 8 + tg * 2;
            uint32_t ch = (uint32_t)(col >> 3);
            uint32_t wi = (uint32_t)((col & 7) * 2);
            #pragma unroll
            for (int r2 = 0; r2 < 2; ++r2) {
                int row = row0 + r2 * 8;
                float v0 = gelu_exact(acc[mi][ni][2 * r2 + 0]);
                float v1 = gelu_exact(acc[mi][ni][2 * r2 + 1]);
                uint32_t h = pack_h2(v0, v1);
                uint32_t a = sb + row * 256 + ((ch ^ (uint32_t)(row & 7)) << 4) + wi;
                asm volatile("st.shared.u32 [%0], %1;" :: "r"(a), "r"(h) : "memory");
            }
        }
    }

    // Phase 2: 64x128x128 single-term MMA (hh*qh), f32 acc, Q double-buffered
    float acc2[4][4][4];
    #pragma unroll
    for (int mi = 0; mi < 4; ++mi)
        #pragma unroll
        for (int ni = 0; ni < 4; ++ni)
            #pragma unroll
            for (int r = 0; r < 4; ++r) acc2[mi][ni][r] = 0.0f;

    for (int kb = 0; kb < 2; ++kb) {
        uint32_t qb = kb ? qb1 : qb0;
        if (kb == 0) { CPA_WAIT1(); } else { CPA_WAIT0(); }
        __syncthreads();   // Q half visible + phase-1 STS visible (kb0)

        #pragma unroll
        for (int ksl = 0; ksl < 4; ++ksl) {
            uint32_t qh[4][2];
            #pragma unroll
            for (int p = 0; p < 2; ++p) {
                int rowB = n0w + p * 16 + rowBoff;
                int cB   = ksl * 2 + cBoff;
                uint32_t aW = qb + rowB * 128
                            + (uint32_t)((cB ^ (rowB & 7)) << 4);
                uint32_t t[4];
                ldsm_x4(aW, t);
                qh[2*p][0] = t[0]; qh[2*p][1] = t[1];
                qh[2*p+1][0] = t[2]; qh[2*p+1][1] = t[3];
            }
            #pragma unroll
            for (int mi = 0; mi < 4; ++mi) {
                int rowA = mi * 16 + rowAoff;
                int cA   = kb * 8 + ksl * 2 + cAoff;
                uint32_t aA = sb + rowA * 256
                            + (uint32_t)((cA ^ (rowA & 7)) << 4);
                uint32_t ah[4];
                ldsm_x4(aA, ah);
                #pragma unroll
                for (int ni = 0; ni < 4; ++ni)
                    mma16816(acc2[mi][ni], ah, qh[ni]);
            }
        }
    }

    // Phase 3: RMS over M=32 (warp's 32 cols = one ii group) + stores
    const int ii = wid;   // 0..3
    #pragma unroll
    for (int mi = 0; mi < 4; ++mi) {
        #pragma unroll
        for (int r2 = 0; r2 < 2; ++r2) {
            int r = mbase + mi * 16 + gq + r2 * 8;
            float ss = 0.0f;
            #pragma unroll
            for (int ni = 0; ni < 4; ++ni) {
                ss = fmaf(acc2[mi][ni][2*r2+0], acc2[mi][ni][2*r2+0], ss);
                ss = fmaf(acc2[mi][ni][2*r2+1], acc2[mi][ni][2*r2+1], ss);
            }
            ss += __shfl_xor_sync(0xffffffffu, ss, 1);
            ss += __shfl_xor_sync(0xffffffffu, ss, 2);

            if (ii < 2) {
                float scale = rsqrtf(ss * (1.0f / 32.0f) + 1e-6f);
                #pragma unroll
                for (int ni = 0; ni < 4; ++ni) {
                    int m = ni * 8 + tg * 2;
                    float2 o = make_float2(acc2[mi][ni][2*r2+0] * scale,
                                           acc2[mi][ni][2*r2+1] * scale);
                    *reinterpret_cast<float2*>(
                        &w1n_out[(size_t)r * 256 + c * 64 + ii * 32 + m]) = o;
                }
            } else {
                #pragma unroll
                for (int ni = 0; ni < 4; ++ni) {
                    int m = ni * 8 + tg * 2;
                    float2 o = make_float2(acc2[mi][ni][2*r2+0],
                                           acc2[mi][ni][2*r2+1]);
                    *reinterpret_cast<float2*>(
                        &w2_out[(size_t)r * 256 + c * 64 + (ii - 2) * 32 + m]) = o;
                }
            }
        }
    }
}

// ---------------------------------------------------------------------------
extern "C" void kernel_launch(void* const* d_in, const int* in_sizes, int n_in,
                              void* d_out, int out_size) {
    const float* query = (const float*)d_in[0];
    // d_in[1] = key_vec (unused by reference)
    const float* dw1   = (const float*)d_in[2];
    const float* qkw   = (const float*)d_in[3];
    const float* dd_p  = (const float*)d_in[4];

    float* out = (float*)d_out;
    float* w1n = out;
    float* w2  = out + W2_BASE;
    float* dd  = out + DD_BASE;

    cudaFuncSetAttribute(gemm_all, cudaFuncAttributeMaxDynamicSharedMemorySize, GEMM1_SMEM);

    conv_wq<<<2624, dim3(32, 8)>>>(dw1, dd_p, qkw);
    gemm_all<<<dim3(4, 128), 128, GEMM1_SMEM>>>(query, w1n, w2, dd);
}